// round 9
// baseline (speedup 1.0000x reference)
#include <cuda_runtime.h>
#include <cuda_fp16.h>
#include <cstdint>
#include <cstddef>

#define DEVINL __device__ __forceinline__

constexpr int JD = 512, VOC = 500, VPAD = 512;
constexpr int NB = 8, TT = 200, UU = 50;
constexpr int ENCR = NB * TT;          // 1600
constexpr int ENCRP = 1664;            // 13*128
constexpr int DECR = NB * UU;          // 400
constexpr int DECRP = 512;             // 4*128
constexpr int ENC_TILES = ENCRP / 128; // 13
constexpr int DEC_TILES = DECRP / 128; // 4
constexpr int MTOT = NB * TT * UU;     // 80000
constexpr int MTILES = MTOT / 128;     // 625

// ---- device scratch (no allocs allowed) ----
__device__ __half g_Wenc[JD * JD];
__device__ __half g_Wdec[JD * JD];
__device__ __half g_Wout[VPAD * JD];
__device__ __half g_Xenc[ENCRP * JD];
__device__ __half g_Xdec[DECRP * JD];
__device__ float  g_enc[ENCRP * JD];
__device__ float  g_dec[DECRP * JD];

// ---- dynamic smem layout (single buffer) ----
constexpr int SM_EOFF = 0;      // 128 int
constexpr int SM_DOFF = 512;    // 128 int
constexpr int SM_BIAS = 1024;   // 512 float
constexpr int SM_A0   = 4096;   // 128x64 f16 sw128 = 16KB
constexpr int SM_B0   = 20480;  // 256x64 f16 sw128 = 32KB
constexpr int SMEM_BYTES = 53248;

DEVINL uint32_t s2u(const void* p) { return (uint32_t)__cvta_generic_to_shared(p); }
DEVINL uint32_t sw128(uint32_t o) { return o ^ ((o >> 3) & 0x70); }
DEVINL float tanh_fast(float x) { float y; asm("tanh.approx.f32 %0, %1;" : "=f"(y) : "f"(x)); return y; }
DEVINL uint32_t h2_bits(__half2 h) { return *reinterpret_cast<uint32_t*>(&h); }

DEVINL void ldsm4(uint32_t* r, uint32_t addr) {
    asm volatile("ldmatrix.sync.aligned.m8n8.x4.shared.b16 {%0,%1,%2,%3}, [%4];"
                 : "=r"(r[0]), "=r"(r[1]), "=r"(r[2]), "=r"(r[3]) : "r"(addr));
}
DEVINL void mma16816(float* c, const uint32_t* a, uint32_t b0, uint32_t b1) {
    asm volatile(
        "mma.sync.aligned.m16n8k16.row.col.f32.f16.f16.f32 "
        "{%0,%1,%2,%3}, {%4,%5,%6,%7}, {%8,%9}, {%0,%1,%2,%3};"
        : "+f"(c[0]), "+f"(c[1]), "+f"(c[2]), "+f"(c[3])
        : "r"(a[0]), "r"(a[1]), "r"(a[2]), "r"(a[3]), "r"(b0), "r"(b1));
}

// ---------------- kernel 1: fp32 -> fp16 convert + zero pad ----------------
__global__ void joiner_convert(const float* __restrict__ xe, const float* __restrict__ xd,
                               const float* __restrict__ we, const float* __restrict__ wd,
                               const float* __restrict__ wo) {
    int i0 = blockIdx.x * blockDim.x + threadIdx.x;
    int st = gridDim.x * blockDim.x;
    for (int i = i0; i < ENCRP * JD; i += st) g_Xenc[i] = __float2half(i < ENCR * JD ? xe[i] : 0.f);
    for (int i = i0; i < DECRP * JD; i += st) g_Xdec[i] = __float2half(i < DECR * JD ? xd[i] : 0.f);
    for (int i = i0; i < JD * JD; i += st) { g_Wenc[i] = __float2half(we[i]); g_Wdec[i] = __float2half(wd[i]); }
    for (int i = i0; i < VPAD * JD; i += st) g_Wout[i] = __float2half(i < VOC * JD ? wo[i] : 0.f);
}

// ---------------- shared HMMA core ----------------
// Computes acc[2][8][4] for this warp from smem A (128x64 f16 sw128) and
// smem B (256x64 f16 sw128). Warp tile 32(M) x 64(N); 512 threads = 16 warps
// arranged 4(M) x 4(N).
struct Frag { float acc[2][8][4]; };

DEVINL void mma_chunk(Frag& f, uint32_t sA, uint32_t sB, int lane, int m0, int n0) {
    int arow = m0 + (lane & 15);
    int acolb = (lane >> 4) * 16;
    int brow = n0 + ((lane >> 4) << 3) + (lane & 7);
    int bcolb = ((lane >> 3) & 1) * 16;
    #pragma unroll
    for (int kk = 0; kk < 4; kk++) {
        uint32_t afr[2][4];
        ldsm4(afr[0], sA + sw128((uint32_t)(arow * 128 + kk * 32 + acolb)));
        ldsm4(afr[1], sA + sw128((uint32_t)((arow + 16) * 128 + kk * 32 + acolb)));
        uint32_t bfr[4][4];
        #pragma unroll
        for (int q = 0; q < 4; q++)
            ldsm4(bfr[q], sB + sw128((uint32_t)((brow + q * 16) * 128 + kk * 32 + bcolb)));
        #pragma unroll
        for (int mt = 0; mt < 2; mt++)
            #pragma unroll
            for (int nt = 0; nt < 8; nt++)
                mma16816(f.acc[mt][nt], afr[mt], bfr[nt >> 1][(nt & 1) * 2], bfr[nt >> 1][(nt & 1) * 2 + 1]);
    }
}

// ---------------- kernel 2: enc & dec projections ----------------
__global__ void __launch_bounds__(512, 1) joiner_proj(const float* __restrict__ be,
                                                      const float* __restrict__ bd) {
    extern __shared__ char smem[];
    uint32_t sb = s2u(smem);
    int tid = threadIdx.x, lane = tid & 31, w = tid >> 5;
    int m0 = (w & 3) * 32, n0 = (w >> 2) * 64;

    bool isenc = (int)blockIdx.x < ENC_TILES;
    int tile = isenc ? blockIdx.x : blockIdx.x - ENC_TILES;
    int nhalf = blockIdx.y;
    const __half* X = (isenc ? g_Xenc : g_Xdec) + (size_t)tile * 128 * JD;
    const __half* W = (isenc ? g_Wenc : g_Wdec) + (size_t)nhalf * 256 * JD;
    const float* bias = isenc ? be : bd;
    float* out = (isenc ? g_enc : g_dec) + (size_t)tile * 128 * JD;

    float* sbias = (float*)(smem + SM_BIAS);
    for (int i = tid; i < 512; i += 512) sbias[i] = bias[i];

    Frag f;
    #pragma unroll
    for (int mt = 0; mt < 2; mt++)
        #pragma unroll
        for (int nt = 0; nt < 8; nt++)
            #pragma unroll
            for (int q = 0; q < 4; q++) f.acc[mt][nt][q] = 0.f;

    for (int c = 0; c < 8; c++) {
        int kc = c * 64;
        __syncthreads();
        #pragma unroll
        for (int i = tid; i < 1024; i += 512) {
            int r = i >> 3, j = i & 7;
            uint4 v = *reinterpret_cast<const uint4*>(X + (size_t)r * JD + kc + j * 8);
            *reinterpret_cast<uint4*>(smem + SM_A0 + sw128(r * 128 + j * 16)) = v;
        }
        #pragma unroll
        for (int i = tid; i < 2048; i += 512) {
            int r = i >> 3, j = i & 7;
            uint4 v = *reinterpret_cast<const uint4*>(W + (size_t)r * JD + kc + j * 8);
            *reinterpret_cast<uint4*>(smem + SM_B0 + sw128(r * 128 + j * 16)) = v;
        }
        __syncthreads();
        mma_chunk(f, sb + SM_A0, sb + SM_B0, lane, m0, n0);
    }

    // epilogue: fp32 + bias -> g_enc/g_dec  (bias indexed by GLOBAL column)
    #pragma unroll
    for (int mt = 0; mt < 2; mt++) {
        int grow = m0 + mt * 16 + (lane >> 2);
        #pragma unroll
        for (int nt = 0; nt < 8; nt++) {
            int col = n0 + nt * 8 + (lane & 3) * 2;
            int gcol = nhalf * 256 + col;
            float2 v0 = { f.acc[mt][nt][0] + sbias[gcol], f.acc[mt][nt][1] + sbias[gcol + 1] };
            float2 v1 = { f.acc[mt][nt][2] + sbias[gcol], f.acc[mt][nt][3] + sbias[gcol + 1] };
            *reinterpret_cast<float2*>(out + (size_t)grow * JD + gcol) = v0;
            *reinterpret_cast<float2*>(out + (size_t)(grow + 8) * JD + gcol) = v1;
        }
    }
}

// ---------------- kernel 3: fused tanh-join + output GEMM ----------------
__global__ void __launch_bounds__(512, 1) joiner_join(const float* __restrict__ bo,
                                                      float* __restrict__ out) {
    extern __shared__ char smem[];
    uint32_t sb = s2u(smem);
    int tid = threadIdx.x, lane = tid & 31, w = tid >> 5;
    int m0 = (w & 3) * 32, n0 = (w >> 2) * 64;
    int tile = blockIdx.x, nhalf = blockIdx.y;

    int* eoff = (int*)(smem + SM_EOFF);
    int* doff = (int*)(smem + SM_DOFF);
    if (tid < 128) {
        int r = tile * 128 + tid;
        int n = r / (TT * UU), rem = r % (TT * UU);
        int t = rem / UU, u = rem % UU;
        eoff[tid] = (n * TT + t) * JD;
        doff[tid] = (n * UU + u) * JD;
    }
    float* sbias = (float*)(smem + SM_BIAS);
    for (int i = tid; i < 512; i += 512) sbias[i] = (i < VOC) ? bo[i] : 0.f;

    const __half* W = g_Wout + (size_t)nhalf * 256 * JD;

    Frag f;
    #pragma unroll
    for (int mt = 0; mt < 2; mt++)
        #pragma unroll
        for (int nt = 0; nt < 8; nt++)
            #pragma unroll
            for (int q = 0; q < 4; q++) f.acc[mt][nt][q] = 0.f;

    for (int c = 0; c < 8; c++) {
        int kc = c * 64;
        __syncthreads();
        // A = fp16(tanh(enc+dec)), 128 rows x 64 k
        #pragma unroll
        for (int i = tid; i < 1024; i += 512) {
            int r = i >> 3, j = i & 7;
            int k = kc + j * 8;
            const float* e = g_enc + eoff[r] + k;
            const float* d = g_dec + doff[r] + k;
            float4 e0 = *reinterpret_cast<const float4*>(e);
            float4 e1 = *reinterpret_cast<const float4*>(e + 4);
            float4 d0 = *reinterpret_cast<const float4*>(d);
            float4 d1 = *reinterpret_cast<const float4*>(d + 4);
            __half2 h0 = __floats2half2_rn(tanh_fast(e0.x + d0.x), tanh_fast(e0.y + d0.y));
            __half2 h1 = __floats2half2_rn(tanh_fast(e0.z + d0.z), tanh_fast(e0.w + d0.w));
            __half2 h2 = __floats2half2_rn(tanh_fast(e1.x + d1.x), tanh_fast(e1.y + d1.y));
            __half2 h3 = __floats2half2_rn(tanh_fast(e1.z + d1.z), tanh_fast(e1.w + d1.w));
            uint4 v;
            v.x = h2_bits(h0); v.y = h2_bits(h1); v.z = h2_bits(h2); v.w = h2_bits(h3);
            *reinterpret_cast<uint4*>(smem + SM_A0 + sw128(r * 128 + j * 16)) = v;
        }
        // B = W_out chunk, 256 rows x 64 k
        #pragma unroll
        for (int i = tid; i < 2048; i += 512) {
            int r = i >> 3, j = i & 7;
            uint4 v = *reinterpret_cast<const uint4*>(W + (size_t)r * JD + kc + j * 8);
            *reinterpret_cast<uint4*>(smem + SM_B0 + sw128(r * 128 + j * 16)) = v;
        }
        __syncthreads();
        mma_chunk(f, sb + SM_A0, sb + SM_B0, lane, m0, n0);
    }

    // epilogue: fp32 + bias -> logits, guard col < VOC
    #pragma unroll
    for (int mt = 0; mt < 2; mt++) {
        int grow = tile * 128 + m0 + mt * 16 + (lane >> 2);
        #pragma unroll
        for (int nt = 0; nt < 8; nt++) {
            int col = n0 + nt * 8 + (lane & 3) * 2;
            int gcol = nhalf * 256 + col;
            if (gcol < VOC) {
                float2 v0 = { f.acc[mt][nt][0] + sbias[gcol], f.acc[mt][nt][1] + sbias[gcol + 1] };
                float2 v1 = { f.acc[mt][nt][2] + sbias[gcol], f.acc[mt][nt][3] + sbias[gcol + 1] };
                *reinterpret_cast<float2*>(out + (size_t)grow * VOC + gcol) = v0;
                *reinterpret_cast<float2*>(out + (size_t)(grow + 8) * VOC + gcol) = v1;
            }
        }
    }
}

extern "C" void kernel_launch(void* const* d_in, const int* in_sizes, int n_in,
                              void* d_out, int out_size) {
    const float* enc = (const float*)d_in[0];
    const float* dec = (const float*)d_in[1];
    const float* We  = (const float*)d_in[2];
    const float* be  = (const float*)d_in[3];
    const float* Wd  = (const float*)d_in[4];
    const float* bd  = (const float*)d_in[5];
    const float* Wo  = (const float*)d_in[6];
    const float* bo  = (const float*)d_in[7];
    float* out = (float*)d_out;

    cudaFuncSetAttribute(joiner_proj, cudaFuncAttributeMaxDynamicSharedMemorySize, SMEM_BYTES);
    cudaFuncSetAttribute(joiner_join, cudaFuncAttributeMaxDynamicSharedMemorySize, SMEM_BYTES);

    joiner_convert<<<592, 256>>>(enc, dec, We, Wd, Wo);
    joiner_proj<<<dim3(ENC_TILES + DEC_TILES, 2), 512, SMEM_BYTES>>>(be, bd);
    joiner_join<<<dim3(MTILES, 2), 512, SMEM_BYTES>>>(bo, out);
}

// round 11
// speedup vs baseline: 1.2057x; 1.2057x over previous
#include <cuda_runtime.h>
#include <cuda_fp16.h>
#include <cstdint>
#include <cstddef>

#define DEVINL __device__ __forceinline__

constexpr int JD = 512, VOC = 500, VPAD = 512;
constexpr int NB = 8, TT = 200, UU = 50;
constexpr int ENCR = NB * TT;          // 1600
constexpr int ENCRP = 1664;            // 13*128
constexpr int DECR = NB * UU;          // 400
constexpr int DECRP = 512;             // 4*128
constexpr int ENC_TILES = ENCRP / 128; // 13
constexpr int DEC_TILES = DECRP / 128; // 4
constexpr int MTOT = NB * TT * UU;     // 80000
constexpr int MTILES = MTOT / 128;     // 625

// ---- device scratch (no allocs allowed) ----
__device__ __align__(16) __half g_Wenc[JD * JD];
__device__ __align__(16) __half g_Wdec[JD * JD];
__device__ __align__(16) __half g_Wout[VPAD * JD];
__device__ __align__(16) __half g_Xenc[ENCRP * JD];
__device__ __align__(16) __half g_Xdec[DECRP * JD];
__device__ __align__(16) float  g_enc[ENCRP * JD];
__device__ __align__(16) float  g_dec[DECRP * JD];

// ---- smem layout: proj kernel (single buffer) ----
constexpr int SM_BIAS = 1024;   // 512 float
constexpr int SM_A0   = 4096;   // 128x64 f16 sw128 = 16KB
constexpr int SM_B0   = 20480;  // 256x64 f16 sw128 = 32KB
constexpr int PROJ_SMEM = 53248;

// ---- smem layout: join kernel (A resident, B double-buffered) ----
constexpr int SM_EOFF = 0;       // 128 int
constexpr int SM_DOFF = 512;     // 128 int
// SM_BIAS shared at 1024
constexpr int JSM_A   = 4096;            // 8 chunks x 16KB = 128KB
constexpr int JSM_B0  = JSM_A + 131072;  // 135168, 32KB
constexpr int JSM_B1  = JSM_B0 + 32768;  // 167936, 32KB
constexpr int JOIN_SMEM = JSM_B1 + 32768; // 200704

DEVINL uint32_t s2u(const void* p) { return (uint32_t)__cvta_generic_to_shared(p); }
DEVINL uint32_t sw128(uint32_t o) { return o ^ ((o >> 3) & 0x70); }
DEVINL float tanh_fast(float x) { float y; asm("tanh.approx.f32 %0, %1;" : "=f"(y) : "f"(x)); return y; }
DEVINL uint32_t h2_bits(__half2 h) { return *reinterpret_cast<uint32_t*>(&h); }

DEVINL void ldsm4(uint32_t* r, uint32_t addr) {
    asm volatile("ldmatrix.sync.aligned.m8n8.x4.shared.b16 {%0,%1,%2,%3}, [%4];"
                 : "=r"(r[0]), "=r"(r[1]), "=r"(r[2]), "=r"(r[3]) : "r"(addr));
}
DEVINL void mma16816(float* c, const uint32_t* a, uint32_t b0, uint32_t b1) {
    asm volatile(
        "mma.sync.aligned.m16n8k16.row.col.f32.f16.f16.f32 "
        "{%0,%1,%2,%3}, {%4,%5,%6,%7}, {%8,%9}, {%0,%1,%2,%3};"
        : "+f"(c[0]), "+f"(c[1]), "+f"(c[2]), "+f"(c[3])
        : "r"(a[0]), "r"(a[1]), "r"(a[2]), "r"(a[3]), "r"(b0), "r"(b1));
}
DEVINL void cpasync16(uint32_t dst, const void* src) {
    asm volatile("cp.async.cg.shared.global [%0], [%1], 16;" :: "r"(dst), "l"(src));
}
DEVINL void cpcommit() { asm volatile("cp.async.commit_group;" ::: "memory"); }
template <int N> DEVINL void cpwait() { asm volatile("cp.async.wait_group %0;" :: "n"(N) : "memory"); }

// ---------------- kernel 1: fp32 -> fp16 convert + zero pad (vectorized) ----------------
DEVINL uint4 pack8(const float* src) {
    float4 a = *reinterpret_cast<const float4*>(src);
    float4 b = *reinterpret_cast<const float4*>(src + 4);
    uint4 o;
    o.x = h2_bits(__floats2half2_rn(a.x, a.y));
    o.y = h2_bits(__floats2half2_rn(a.z, a.w));
    o.z = h2_bits(__floats2half2_rn(b.x, b.y));
    o.w = h2_bits(__floats2half2_rn(b.z, b.w));
    return o;
}
__global__ void joiner_convert(const float* __restrict__ xe, const float* __restrict__ xd,
                               const float* __restrict__ we, const float* __restrict__ wd,
                               const float* __restrict__ wo) {
    int i0 = blockIdx.x * blockDim.x + threadIdx.x;
    int st = gridDim.x * blockDim.x;
    const uint4 z = {0, 0, 0, 0};
    for (int i = i0; i < ENCRP * JD / 8; i += st)
        reinterpret_cast<uint4*>(g_Xenc)[i] = (i < ENCR * JD / 8) ? pack8(xe + i * 8) : z;
    for (int i = i0; i < DECRP * JD / 8; i += st)
        reinterpret_cast<uint4*>(g_Xdec)[i] = (i < DECR * JD / 8) ? pack8(xd + i * 8) : z;
    for (int i = i0; i < JD * JD / 8; i += st) {
        reinterpret_cast<uint4*>(g_Wenc)[i] = pack8(we + i * 8);
        reinterpret_cast<uint4*>(g_Wdec)[i] = pack8(wd + i * 8);
    }
    for (int i = i0; i < VPAD * JD / 8; i += st)
        reinterpret_cast<uint4*>(g_Wout)[i] = (i < VOC * JD / 8) ? pack8(wo + i * 8) : z;
}

// ---------------- shared HMMA core ----------------
// Warp tile 32(M) x 64(N); 512 threads = 16 warps arranged 4(M) x 4(N).
struct Frag { float acc[2][8][4]; };

DEVINL void frag_zero(Frag& f) {
    #pragma unroll
    for (int mt = 0; mt < 2; mt++)
        #pragma unroll
        for (int nt = 0; nt < 8; nt++)
            #pragma unroll
            for (int q = 0; q < 4; q++) f.acc[mt][nt][q] = 0.f;
}

DEVINL void mma_chunk(Frag& f, uint32_t sA, uint32_t sB, int lane, int m0, int n0) {
    int arow = m0 + (lane & 15);
    int acolb = (lane >> 4) * 16;
    int brow = n0 + ((lane >> 4) << 3) + (lane & 7);
    int bcolb = ((lane >> 3) & 1) * 16;
    #pragma unroll
    for (int kk = 0; kk < 4; kk++) {
        uint32_t afr[2][4];
        ldsm4(afr[0], sA + sw128((uint32_t)(arow * 128 + kk * 32 + acolb)));
        ldsm4(afr[1], sA + sw128((uint32_t)((arow + 16) * 128 + kk * 32 + acolb)));
        uint32_t bfr[4][4];
        #pragma unroll
        for (int q = 0; q < 4; q++)
            ldsm4(bfr[q], sB + sw128((uint32_t)((brow + q * 16) * 128 + kk * 32 + bcolb)));
        #pragma unroll
        for (int mt = 0; mt < 2; mt++)
            #pragma unroll
            for (int nt = 0; nt < 8; nt++)
                mma16816(f.acc[mt][nt], afr[mt], bfr[nt >> 1][(nt & 1) * 2], bfr[nt >> 1][(nt & 1) * 2 + 1]);
    }
}

// ---------------- kernel 2: enc & dec projections ----------------
__global__ void __launch_bounds__(512, 1) joiner_proj(const float* __restrict__ be,
                                                      const float* __restrict__ bd) {
    extern __shared__ char smem[];
    uint32_t sb = s2u(smem);
    int tid = threadIdx.x, lane = tid & 31, w = tid >> 5;
    int m0 = (w & 3) * 32, n0 = (w >> 2) * 64;

    bool isenc = (int)blockIdx.x < ENC_TILES;
    int tile = isenc ? blockIdx.x : blockIdx.x - ENC_TILES;
    int nhalf = blockIdx.y;
    const __half* X = (isenc ? g_Xenc : g_Xdec) + (size_t)tile * 128 * JD;
    const __half* W = (isenc ? g_Wenc : g_Wdec) + (size_t)nhalf * 256 * JD;
    const float* bias = isenc ? be : bd;
    float* out = (isenc ? g_enc : g_dec) + (size_t)tile * 128 * JD;

    float* sbias = (float*)(smem + SM_BIAS);
    for (int i = tid; i < 512; i += 512) sbias[i] = bias[i];

    Frag f;
    frag_zero(f);

    for (int c = 0; c < 8; c++) {
        int kc = c * 64;
        __syncthreads();
        #pragma unroll
        for (int i = tid; i < 1024; i += 512) {
            int r = i >> 3, j = i & 7;
            uint4 v = *reinterpret_cast<const uint4*>(X + (size_t)r * JD + kc + j * 8);
            *reinterpret_cast<uint4*>(smem + SM_A0 + sw128(r * 128 + j * 16)) = v;
        }
        #pragma unroll
        for (int i = tid; i < 2048; i += 512) {
            int r = i >> 3, j = i & 7;
            uint4 v = *reinterpret_cast<const uint4*>(W + (size_t)r * JD + kc + j * 8);
            *reinterpret_cast<uint4*>(smem + SM_B0 + sw128(r * 128 + j * 16)) = v;
        }
        __syncthreads();
        mma_chunk(f, sb + SM_A0, sb + SM_B0, lane, m0, n0);
    }

    #pragma unroll
    for (int mt = 0; mt < 2; mt++) {
        int grow = m0 + mt * 16 + (lane >> 2);
        #pragma unroll
        for (int nt = 0; nt < 8; nt++) {
            int col = n0 + nt * 8 + (lane & 3) * 2;
            int gcol = nhalf * 256 + col;
            float2 v0 = { f.acc[mt][nt][0] + sbias[gcol], f.acc[mt][nt][1] + sbias[gcol + 1] };
            float2 v1 = { f.acc[mt][nt][2] + sbias[gcol], f.acc[mt][nt][3] + sbias[gcol + 1] };
            *reinterpret_cast<float2*>(out + (size_t)grow * JD + gcol) = v0;
            *reinterpret_cast<float2*>(out + (size_t)(grow + 8) * JD + gcol) = v1;
        }
    }
}

// ---------------- kernel 3: fused tanh-join + output GEMM ----------------
DEVINL void issueB(uint32_t sb, int buf, int nh, int c, int tid) {
    const __half* W = g_Wout + (size_t)nh * 256 * JD + c * 64;
    uint32_t base = sb + (buf ? JSM_B1 : JSM_B0);
    #pragma unroll
    for (int i = tid; i < 2048; i += 512) {
        int r = i >> 3, j = i & 7;
        cpasync16(base + sw128((uint32_t)(r * 128 + j * 16)), W + (size_t)r * JD + j * 8);
    }
    cpcommit();
}

__global__ void __launch_bounds__(512, 1) joiner_join(const float* __restrict__ bo,
                                                      float* __restrict__ out) {
    extern __shared__ char smem[];
    uint32_t sb = s2u(smem);
    int tid = threadIdx.x, lane = tid & 31, w = tid >> 5;
    int m0 = (w & 3) * 32, n0 = (w >> 2) * 64;
    int tile = blockIdx.x;

    int* eoff = (int*)(smem + SM_EOFF);
    int* doff = (int*)(smem + SM_DOFF);
    if (tid < 128) {
        int r = tile * 128 + tid;
        int n = r / (TT * UU), rem = r % (TT * UU);
        int t = rem / UU, u = rem % UU;
        eoff[tid] = (n * TT + t) * JD;
        doff[tid] = (n * UU + u) * JD;
    }
    float* sbias = (float*)(smem + SM_BIAS);
    for (int i = tid; i < 512; i += 512) sbias[i] = (i < VOC) ? bo[i] : 0.f;

    // prefetch first B chunk while generating A
    issueB(sb, 0, 0, 0, tid);

    __syncthreads();  // eoff/doff visible

    // generate full A = fp16(tanh(enc+dec)): 128 rows x 512 cols, 8 sw128 chunks
    for (int i = tid; i < 8192; i += 512) {
        int r = i >> 6, j = i & 63;
        int c = j >> 3, jj = j & 7;
        int k = j * 8;
        const float* e = g_enc + eoff[r] + k;
        const float* d = g_dec + doff[r] + k;
        float4 e0 = *reinterpret_cast<const float4*>(e);
        float4 e1 = *reinterpret_cast<const float4*>(e + 4);
        float4 d0 = *reinterpret_cast<const float4*>(d);
        float4 d1 = *reinterpret_cast<const float4*>(d + 4);
        uint4 v;
        v.x = h2_bits(__floats2half2_rn(tanh_fast(e0.x + d0.x), tanh_fast(e0.y + d0.y)));
        v.y = h2_bits(__floats2half2_rn(tanh_fast(e0.z + d0.z), tanh_fast(e0.w + d0.w)));
        v.z = h2_bits(__floats2half2_rn(tanh_fast(e1.x + d1.x), tanh_fast(e1.y + d1.y)));
        v.w = h2_bits(__floats2half2_rn(tanh_fast(e1.z + d1.z), tanh_fast(e1.w + d1.w)));
        *reinterpret_cast<uint4*>(smem + JSM_A + c * 16384 + sw128(r * 128 + jj * 16)) = v;
    }
    __syncthreads();  // A visible to all warps

    Frag f;
    frag_zero(f);

    for (int s = 0; s < 16; s++) {
        int nh = s >> 3, c = s & 7, buf = s & 1;
        if (s < 15) {
            issueB(sb, buf ^ 1, (s + 1) >> 3, (s + 1) & 7, tid);
            cpwait<1>();
        } else {
            cpwait<0>();
        }
        __syncthreads();  // B[buf] ready for all warps
        mma_chunk(f, sb + JSM_A + c * 16384, sb + (buf ? JSM_B1 : JSM_B0), lane, m0, n0);

        if (c == 7) {
            // epilogue for this N-half, then reset accumulators
            #pragma unroll
            for (int mt = 0; mt < 2; mt++) {
                int grow = tile * 128 + m0 + mt * 16 + (lane >> 2);
                #pragma unroll
                for (int nt = 0; nt < 8; nt++) {
                    int col = n0 + nt * 8 + (lane & 3) * 2;
                    int gcol = nh * 256 + col;
                    if (gcol < VOC) {
                        float2 v0 = { f.acc[mt][nt][0] + sbias[gcol], f.acc[mt][nt][1] + sbias[gcol + 1] };
                        float2 v1 = { f.acc[mt][nt][2] + sbias[gcol], f.acc[mt][nt][3] + sbias[gcol + 1] };
                        *reinterpret_cast<float2*>(out + (size_t)grow * VOC + gcol) = v0;
                        *reinterpret_cast<float2*>(out + (size_t)(grow + 8) * VOC + gcol) = v1;
                    }
                }
            }
            frag_zero(f);
        }
        __syncthreads();  // all warps done reading B[buf] before it is refilled
    }
}

extern "C" void kernel_launch(void* const* d_in, const int* in_sizes, int n_in,
                              void* d_out, int out_size) {
    const float* enc = (const float*)d_in[0];
    const float* dec = (const float*)d_in[1];
    const float* We  = (const float*)d_in[2];
    const float* be  = (const float*)d_in[3];
    const float* Wd  = (const float*)d_in[4];
    const float* bd  = (const float*)d_in[5];
    const float* Wo  = (const float*)d_in[6];
    const float* bo  = (const float*)d_in[7];
    float* out = (float*)d_out;

    cudaFuncSetAttribute(joiner_proj, cudaFuncAttributeMaxDynamicSharedMemorySize, PROJ_SMEM);
    cudaFuncSetAttribute(joiner_join, cudaFuncAttributeMaxDynamicSharedMemorySize, JOIN_SMEM);

    joiner_convert<<<416, 256>>>(enc, dec, We, Wd, Wo);
    joiner_proj<<<dim3(ENC_TILES + DEC_TILES, 2), 512, PROJ_SMEM>>>(be, bd);
    joiner_join<<<MTILES, 512, JOIN_SMEM>>>(bo, out);
}

// round 13
// speedup vs baseline: 1.2408x; 1.0291x over previous
#include <cuda_runtime.h>
#include <cuda_fp16.h>
#include <cstdint>
#include <cstddef>

#define DEVINL __device__ __forceinline__

constexpr int JD = 512, VOC = 500, VPAD = 512;
constexpr int NB = 8, TT = 200, UU = 50;
constexpr int ENCR = NB * TT;          // 1600
constexpr int ENCRP = 1664;            // 13*128
constexpr int DECR = NB * UU;          // 400
constexpr int ENC_TILES = ENCRP / 128; // 13
constexpr int DEC_TILES = 4;           // 512/128
constexpr int PROJ_TILES = ENC_TILES + DEC_TILES; // 17
constexpr int MTOT = NB * TT * UU;     // 80000
constexpr int JT_M = 64;
constexpr int JTILES = MTOT / JT_M;    // 1250

// ---- device scratch (no allocs allowed) ----
__device__ __align__(16) __half g_Wout[VPAD * JD];
__device__ __align__(16) float  g_enc[ENCRP * JD];
__device__ __align__(16) float  g_dec[512 * JD];

// ---- smem layout: proj kernel (single buffer) ----
constexpr int SM_BIAS = 1024;   // 512 float
constexpr int SM_A0   = 4096;   // 128x64 f16 sw128 = 16KB
constexpr int SM_B0   = 20480;  // 256x64 f16 sw128 = 32KB
constexpr int PROJ_SMEM = 53248;

// ---- smem layout: join kernel (A + B double buffered) ----
constexpr int JSM_EOFF = 0;      // 64 int
constexpr int JSM_DOFF = 256;    // 64 int
constexpr int JSM_BIAS = 1024;   // 512 float
constexpr int JSM_A0   = 4096;   // 64x64 f16 sw128 = 8KB
constexpr int JSM_A1   = 12288;
constexpr int JSM_B0   = 20480;  // 256x64 f16 sw128 = 32KB
constexpr int JSM_B1   = 53248;
constexpr int JOIN_SMEM = 86016; // fits 2 CTAs/SM

DEVINL uint32_t s2u(const void* p) { return (uint32_t)__cvta_generic_to_shared(p); }
DEVINL uint32_t sw128(uint32_t o) { return o ^ ((o >> 3) & 0x70); }
DEVINL float tanh_fast(float x) { float y; asm("tanh.approx.f32 %0, %1;" : "=f"(y) : "f"(x)); return y; }
DEVINL uint32_t h2_bits(__half2 h) { return *reinterpret_cast<uint32_t*>(&h); }

DEVINL void ldsm4(uint32_t* r, uint32_t addr) {
    asm volatile("ldmatrix.sync.aligned.m8n8.x4.shared.b16 {%0,%1,%2,%3}, [%4];"
                 : "=r"(r[0]), "=r"(r[1]), "=r"(r[2]), "=r"(r[3]) : "r"(addr));
}
DEVINL void mma16816(float* c, const uint32_t* a, uint32_t b0, uint32_t b1) {
    asm volatile(
        "mma.sync.aligned.m16n8k16.row.col.f32.f16.f16.f32 "
        "{%0,%1,%2,%3}, {%4,%5,%6,%7}, {%8,%9}, {%0,%1,%2,%3};"
        : "+f"(c[0]), "+f"(c[1]), "+f"(c[2]), "+f"(c[3])
        : "r"(a[0]), "r"(a[1]), "r"(a[2]), "r"(a[3]), "r"(b0), "r"(b1));
}
DEVINL void cpasync16(uint32_t dst, const void* src) {
    asm volatile("cp.async.cg.shared.global [%0], [%1], 16;" :: "r"(dst), "l"(src));
}
DEVINL void cpcommit() { asm volatile("cp.async.commit_group;" ::: "memory"); }
template <int N> DEVINL void cpwait() { asm volatile("cp.async.wait_group %0;" :: "n"(N) : "memory"); }

DEVINL uint4 pack8(const float* src) {
    float4 a = *reinterpret_cast<const float4*>(src);
    float4 b = *reinterpret_cast<const float4*>(src + 4);
    uint4 o;
    o.x = h2_bits(__floats2half2_rn(a.x, a.y));
    o.y = h2_bits(__floats2half2_rn(a.z, a.w));
    o.z = h2_bits(__floats2half2_rn(b.x, b.y));
    o.w = h2_bits(__floats2half2_rn(b.z, b.w));
    return o;
}

// ---------------- shared HMMA core ----------------
struct Frag { float acc[2][8][4]; };

DEVINL void frag_zero(Frag& f) {
    #pragma unroll
    for (int mt = 0; mt < 2; mt++)
        #pragma unroll
        for (int nt = 0; nt < 8; nt++)
            #pragma unroll
            for (int q = 0; q < 4; q++) f.acc[mt][nt][q] = 0.f;
}

// Warp tile 32(M) x 64(N) over one 64-K chunk in sw128 smem.
DEVINL void mma_chunk(Frag& f, uint32_t sA, uint32_t sB, int lane, int m0, int n0) {
    int arow = m0 + (lane & 15);
    int acolb = (lane >> 4) * 16;
    int brow = n0 + ((lane >> 4) << 3) + (lane & 7);
    int bcolb = ((lane >> 3) & 1) * 16;
    #pragma unroll
    for (int kk = 0; kk < 4; kk++) {
        uint32_t afr[2][4];
        ldsm4(afr[0], sA + sw128((uint32_t)(arow * 128 + kk * 32 + acolb)));
        ldsm4(afr[1], sA + sw128((uint32_t)((arow + 16) * 128 + kk * 32 + acolb)));
        uint32_t bfr[4][4];
        #pragma unroll
        for (int q = 0; q < 4; q++)
            ldsm4(bfr[q], sB + sw128((uint32_t)((brow + q * 16) * 128 + kk * 32 + bcolb)));
        #pragma unroll
        for (int mt = 0; mt < 2; mt++)
            #pragma unroll
            for (int nt = 0; nt < 8; nt++)
                mma16816(f.acc[mt][nt], afr[mt], bfr[nt >> 1][(nt & 1) * 2], bfr[nt >> 1][(nt & 1) * 2 + 1]);
    }
}

// ---------------- kernel 1: projections (inline fp32->f16) + Wout convert ----------------
__global__ void __launch_bounds__(512, 1) joiner_proj(
    const float* __restrict__ xe, const float* __restrict__ xd,
    const float* __restrict__ we, const float* __restrict__ wd,
    const float* __restrict__ wo,
    const float* __restrict__ be, const float* __restrict__ bd) {
    extern __shared__ char smem[];
    uint32_t sb = s2u(smem);
    int tid = threadIdx.x, lane = tid & 31, w = tid >> 5;

    // trailing blocks: convert W_out to f16 (zero-padded rows >= VOC)
    if ((int)blockIdx.x >= PROJ_TILES) {
        int cid = ((int)blockIdx.x - PROJ_TILES) * 2 + blockIdx.y;  // 0..3
        const uint4 z = {0, 0, 0, 0};
        int base = cid * (128 * JD / 8);
        for (int i = tid; i < 128 * JD / 8; i += 512) {
            int idx = base + i;
            reinterpret_cast<uint4*>(g_Wout)[idx] = (idx < VOC * JD / 8) ? pack8(wo + (size_t)idx * 8) : z;
        }
        return;
    }

    int m0 = (w & 3) * 32, n0 = (w >> 2) * 64;
    bool isenc = (int)blockIdx.x < ENC_TILES;
    int tile = isenc ? blockIdx.x : blockIdx.x - ENC_TILES;
    int nhalf = blockIdx.y;
    const float* Xf = (isenc ? xe : xd) + (size_t)tile * 128 * JD;
    const float* Wf = (isenc ? we : wd) + (size_t)nhalf * 256 * JD;
    int xrows = (isenc ? ENCR : DECR) - tile * 128;  // valid rows in this tile
    const float* bias = isenc ? be : bd;
    float* out = (isenc ? g_enc : g_dec) + (size_t)tile * 128 * JD;

    float* sbias = (float*)(smem + SM_BIAS);
    for (int i = tid; i < 512; i += 512) sbias[i] = bias[i];

    Frag f;
    frag_zero(f);
    const uint4 z = {0, 0, 0, 0};

    for (int c = 0; c < 8; c++) {
        int kc = c * 64;
        __syncthreads();
        #pragma unroll
        for (int i = tid; i < 1024; i += 512) {
            int r = i >> 3, j = i & 7;
            uint4 v = (r < xrows) ? pack8(Xf + (size_t)r * JD + kc + j * 8) : z;
            *reinterpret_cast<uint4*>(smem + SM_A0 + sw128(r * 128 + j * 16)) = v;
        }
        #pragma unroll
        for (int i = tid; i < 2048; i += 512) {
            int r = i >> 3, j = i & 7;
            uint4 v = pack8(Wf + (size_t)r * JD + kc + j * 8);
            *reinterpret_cast<uint4*>(smem + SM_B0 + sw128(r * 128 + j * 16)) = v;
        }
        __syncthreads();
        mma_chunk(f, sb + SM_A0, sb + SM_B0, lane, m0, n0);
    }

    #pragma unroll
    for (int mt = 0; mt < 2; mt++) {
        int grow = m0 + mt * 16 + (lane >> 2);
        #pragma unroll
        for (int nt = 0; nt < 8; nt++) {
            int col = n0 + nt * 8 + (lane & 3) * 2;
            int gcol = nhalf * 256 + col;
            float2 v0 = { f.acc[mt][nt][0] + sbias[gcol], f.acc[mt][nt][1] + sbias[gcol + 1] };
            float2 v1 = { f.acc[mt][nt][2] + sbias[gcol], f.acc[mt][nt][3] + sbias[gcol + 1] };
            *reinterpret_cast<float2*>(out + (size_t)grow * JD + gcol) = v0;
            *reinterpret_cast<float2*>(out + (size_t)(grow + 8) * JD + gcol) = v1;
        }
    }
}

// ---------------- kernel 2: fused tanh-join + output GEMM (2 CTAs/SM) ----------------
DEVINL void issueB(uint32_t sb, int buf, int nh, int c, int tid) {
    const __half* W = g_Wout + (size_t)nh * 256 * JD + c * 64;
    uint32_t base = sb + (buf ? JSM_B1 : JSM_B0);
    #pragma unroll
    for (int i = tid; i < 2048; i += 256) {
        int r = i >> 3, j = i & 7;
        cpasync16(base + sw128((uint32_t)(r * 128 + j * 16)), W + (size_t)r * JD + j * 8);
    }
    cpcommit();
}

DEVINL void genA(char* smem, int abase, const int* eoff, const int* doff, int c, int tid) {
    #pragma unroll
    for (int i = tid; i < 512; i += 256) {
        int r = i >> 3, j = i & 7;
        int k = c * 64 + j * 8;
        const float* e = g_enc + eoff[r] + k;
        const float* d = g_dec + doff[r] + k;
        float4 e0 = *reinterpret_cast<const float4*>(e);
        float4 e1 = *reinterpret_cast<const float4*>(e + 4);
        float4 d0 = *reinterpret_cast<const float4*>(d);
        float4 d1 = *reinterpret_cast<const float4*>(d + 4);
        uint4 v;
        v.x = h2_bits(__floats2half2_rn(tanh_fast(e0.x + d0.x), tanh_fast(e0.y + d0.y)));
        v.y = h2_bits(__floats2half2_rn(tanh_fast(e0.z + d0.z), tanh_fast(e0.w + d0.w)));
        v.z = h2_bits(__floats2half2_rn(tanh_fast(e1.x + d1.x), tanh_fast(e1.y + d1.y)));
        v.w = h2_bits(__floats2half2_rn(tanh_fast(e1.z + d1.z), tanh_fast(e1.w + d1.w)));
        *reinterpret_cast<uint4*>(smem + abase + sw128(r * 128 + j * 16)) = v;
    }
}

__global__ void __launch_bounds__(256, 2) joiner_join(const float* __restrict__ bo,
                                                      float* __restrict__ out) {
    extern __shared__ char smem[];
    uint32_t sb = s2u(smem);
    int tid = threadIdx.x, lane = tid & 31, w = tid >> 5;
    int m0 = (w & 1) * 32, n0 = (w >> 1) * 64;
    int tile = blockIdx.x;

    int* eoff = (int*)(smem + JSM_EOFF);
    int* doff = (int*)(smem + JSM_DOFF);
    if (tid < 64) {
        int r = tile * JT_M + tid;
        int n = r / (TT * UU), rem = r % (TT * UU);
        int t = rem / UU, u = rem % UU;
        eoff[tid] = (n * TT + t) * JD;
        doff[tid] = (n * UU + u) * JD;
    }
    float* sbias = (float*)(smem + JSM_BIAS);
    for (int i = tid; i < 512; i += 256) sbias[i] = (i < VOC) ? bo[i] : 0.f;

    issueB(sb, 0, 0, 0, tid);   // B stage 0 (async)
    __syncthreads();            // eoff/doff visible
    genA(smem, JSM_A0, eoff, doff, 0, tid);

    Frag f;
    frag_zero(f);

    for (int s = 0; s < 16; s++) {
        int nh = s >> 3, c = s & 7, buf = s & 1;
        if (s < 15) {
            genA(smem, buf ? JSM_A0 : JSM_A1, eoff, doff, (s + 1) & 7, tid);
            issueB(sb, buf ^ 1, (s + 1) >> 3, (s + 1) & 7, tid);
            cpwait<1>();
        } else {
            cpwait<0>();
        }
        __syncthreads();  // B[s] + A[s] published to all warps
        mma_chunk(f, sb + (buf ? JSM_A1 : JSM_A0), sb + (buf ? JSM_B1 : JSM_B0), lane, m0, n0);

        if (c == 7) {
            #pragma unroll
            for (int mt = 0; mt < 2; mt++) {
                int grow = tile * JT_M + m0 + mt * 16 + (lane >> 2);
                #pragma unroll
                for (int nt = 0; nt < 8; nt++) {
                    int col = n0 + nt * 8 + (lane & 3) * 2;
                    int gcol = nh * 256 + col;
                    if (gcol < VOC) {
                        float2 v0 = { f.acc[mt][nt][0] + sbias[gcol], f.acc[mt][nt][1] + sbias[gcol + 1] };
                        float2 v1 = { f.acc[mt][nt][2] + sbias[gcol], f.acc[mt][nt][3] + sbias[gcol + 1] };
                        *reinterpret_cast<float2*>(out + (size_t)grow * VOC + gcol) = v0;
                        *reinterpret_cast<float2*>(out + (size_t)(grow + 8) * VOC + gcol) = v1;
                    }
                }
            }
            frag_zero(f);
        }
        __syncthreads();  // all warps done with stage-s buffers before refill
    }
}

extern "C" void kernel_launch(void* const* d_in, const int* in_sizes, int n_in,
                              void* d_out, int out_size) {
    const float* enc = (const float*)d_in[0];
    const float* dec = (const float*)d_in[1];
    const float* We  = (const float*)d_in[2];
    const float* be  = (const float*)d_in[3];
    const float* Wd  = (const float*)d_in[4];
    const float* bd  = (const float*)d_in[5];
    const float* Wo  = (const float*)d_in[6];
    const float* bo  = (const float*)d_in[7];
    float* out = (float*)d_out;

    cudaFuncSetAttribute(joiner_proj, cudaFuncAttributeMaxDynamicSharedMemorySize, PROJ_SMEM);
    cudaFuncSetAttribute(joiner_join, cudaFuncAttributeMaxDynamicSharedMemorySize, JOIN_SMEM);

    joiner_proj<<<dim3(PROJ_TILES + 2, 2), 512, PROJ_SMEM>>>(enc, dec, We, Wd, Wo, be, bd);
    joiner_join<<<JTILES, 256, JOIN_SMEM>>>(bo, out);
}

// round 14
// speedup vs baseline: 1.2521x; 1.0091x over previous
#include <cuda_runtime.h>
#include <cuda_fp16.h>
#include <cstdint>
#include <cstddef>

#define DEVINL __device__ __forceinline__

constexpr int JD = 512, VOC = 500, VPAD = 512;
constexpr int NB = 8, TT = 200, UU = 50;
constexpr int ENCR = NB * TT;          // 1600
constexpr int ENCRP = 1664;            // 13*128
constexpr int DECR = NB * UU;          // 400
constexpr int ENC_TILES = ENCRP / 128; // 13
constexpr int DEC_TILES = 4;           // 512/128
constexpr int PROJ_TILES = ENC_TILES + DEC_TILES; // 17
constexpr int MTOT = NB * TT * UU;     // 80000
constexpr int JT_M = 64;
constexpr int JTILES = MTOT / JT_M;    // 1250

// ---- device scratch (no allocs allowed) ----
__device__ __align__(16) __half g_Wout[VPAD * JD];
__device__ __align__(16) float  g_enc[ENCRP * JD];
__device__ __align__(16) float  g_dec[512 * JD];

// ---- smem layout: proj kernel ----
constexpr int SM_BIAS = 1024;   // 512 float
constexpr int SM_A0   = 4096;   // 128x64 f16 sw128 = 16KB
constexpr int SM_B0   = 20480;  // 128x64 f16 sw128 = 16KB
constexpr int PROJ_SMEM = 36864;

// ---- smem layout: join kernel (A resident, B K32 double-buffered) ----
constexpr int JSM_EOFF = 0;      // 64 int
constexpr int JSM_DOFF = 256;    // 64 int
constexpr int JSM_BIAS = 1024;   // 512 float
constexpr int JSM_A    = 4096;           // 8 chunks x (64x64 f16 sw128 = 8KB) = 64KB
constexpr int JSM_B0   = JSM_A + 65536;  // 69632, 256x32 f16 sw64 = 16KB
constexpr int JSM_B1   = JSM_B0 + 16384; // 86016
constexpr int JOIN_SMEM = JSM_B1 + 16384; // 102400 -> 2 CTAs/SM

DEVINL uint32_t s2u(const void* p) { return (uint32_t)__cvta_generic_to_shared(p); }
DEVINL uint32_t sw128(uint32_t o) { return o ^ ((o >> 3) & 0x70); }
DEVINL uint32_t sw64(uint32_t o)  { return o ^ ((o >> 3) & 0x30); }
DEVINL float tanh_fast(float x) { float y; asm("tanh.approx.f32 %0, %1;" : "=f"(y) : "f"(x)); return y; }
DEVINL uint32_t h2_bits(__half2 h) { return *reinterpret_cast<uint32_t*>(&h); }

DEVINL void ldsm4(uint32_t* r, uint32_t addr) {
    asm volatile("ldmatrix.sync.aligned.m8n8.x4.shared.b16 {%0,%1,%2,%3}, [%4];"
                 : "=r"(r[0]), "=r"(r[1]), "=r"(r[2]), "=r"(r[3]) : "r"(addr));
}
DEVINL void mma16816(float* c, const uint32_t* a, uint32_t b0, uint32_t b1) {
    asm volatile(
        "mma.sync.aligned.m16n8k16.row.col.f32.f16.f16.f32 "
        "{%0,%1,%2,%3}, {%4,%5,%6,%7}, {%8,%9}, {%0,%1,%2,%3};"
        : "+f"(c[0]), "+f"(c[1]), "+f"(c[2]), "+f"(c[3])
        : "r"(a[0]), "r"(a[1]), "r"(a[2]), "r"(a[3]), "r"(b0), "r"(b1));
}
DEVINL void cpasync16(uint32_t dst, const void* src) {
    asm volatile("cp.async.cg.shared.global [%0], [%1], 16;" :: "r"(dst), "l"(src));
}
DEVINL void cpcommit() { asm volatile("cp.async.commit_group;" ::: "memory"); }
template <int N> DEVINL void cpwait() { asm volatile("cp.async.wait_group %0;" :: "n"(N) : "memory"); }

DEVINL uint4 pack8(const float* src) {
    float4 a = *reinterpret_cast<const float4*>(src);
    float4 b = *reinterpret_cast<const float4*>(src + 4);
    uint4 o;
    o.x = h2_bits(__floats2half2_rn(a.x, a.y));
    o.y = h2_bits(__floats2half2_rn(a.z, a.w));
    o.z = h2_bits(__floats2half2_rn(b.x, b.y));
    o.w = h2_bits(__floats2half2_rn(b.z, b.w));
    return o;
}

// ---------------- HMMA fragments ----------------
struct Frag { float acc[2][8][4]; };

DEVINL void frag_zero(Frag& f) {
    #pragma unroll
    for (int mt = 0; mt < 2; mt++)
        #pragma unroll
        for (int nt = 0; nt < 8; nt++)
            #pragma unroll
            for (int q = 0; q < 4; q++) f.acc[mt][nt][q] = 0.f;
}

// K=64 chunk, A+B both sw128 128B rows (proj kernel). Warp tile 32Mx64N.
DEVINL void mma_chunk64(Frag& f, uint32_t sA, uint32_t sB, int lane, int m0, int n0) {
    int arow = m0 + (lane & 15);
    int acolb = (lane >> 4) * 16;
    int brow = n0 + ((lane >> 4) << 3) + (lane & 7);
    int bcolb = ((lane >> 3) & 1) * 16;
    #pragma unroll
    for (int kk = 0; kk < 4; kk++) {
        uint32_t afr[2][4];
        ldsm4(afr[0], sA + sw128((uint32_t)(arow * 128 + kk * 32 + acolb)));
        ldsm4(afr[1], sA + sw128((uint32_t)((arow + 16) * 128 + kk * 32 + acolb)));
        uint32_t bfr[4][4];
        #pragma unroll
        for (int q = 0; q < 4; q++)
            ldsm4(bfr[q], sB + sw128((uint32_t)((brow + q * 16) * 128 + kk * 32 + bcolb)));
        #pragma unroll
        for (int mt = 0; mt < 2; mt++)
            #pragma unroll
            for (int nt = 0; nt < 8; nt++)
                mma16816(f.acc[mt][nt], afr[mt], bfr[nt >> 1][(nt & 1) * 2], bfr[nt >> 1][(nt & 1) * 2 + 1]);
    }
}

// K=32 stage (join): A sw128 128B rows with byte offset koff; B sw64 64B rows.
DEVINL void mma_chunk32(Frag& f, uint32_t sA, int koff, uint32_t sB, int lane, int m0, int n0) {
    int arow = m0 + (lane & 15);
    int acolb = (lane >> 4) * 16;
    int brow = n0 + ((lane >> 4) << 3) + (lane & 7);
    int bcolb = ((lane >> 3) & 1) * 16;
    #pragma unroll
    for (int kk = 0; kk < 2; kk++) {
        uint32_t afr[2][4];
        ldsm4(afr[0], sA + sw128((uint32_t)(arow * 128 + koff + kk * 32 + acolb)));
        ldsm4(afr[1], sA + sw128((uint32_t)((arow + 16) * 128 + koff + kk * 32 + acolb)));
        uint32_t bfr[4][4];
        #pragma unroll
        for (int q = 0; q < 4; q++)
            ldsm4(bfr[q], sB + sw64((uint32_t)((brow + q * 16) * 64 + kk * 32 + bcolb)));
        #pragma unroll
        for (int mt = 0; mt < 2; mt++)
            #pragma unroll
            for (int nt = 0; nt < 8; nt++)
                mma16816(f.acc[mt][nt], afr[mt], bfr[nt >> 1][(nt & 1) * 2], bfr[nt >> 1][(nt & 1) * 2 + 1]);
    }
}

// ---------------- kernel 1: projections (inline fp32->f16) + Wout convert ----------------
__global__ void __launch_bounds__(256, 2) joiner_proj(
    const float* __restrict__ xe, const float* __restrict__ xd,
    const float* __restrict__ we, const float* __restrict__ wd,
    const float* __restrict__ wo,
    const float* __restrict__ be, const float* __restrict__ bd) {
    extern __shared__ char smem[];
    uint32_t sb = s2u(smem);
    int tid = threadIdx.x, lane = tid & 31, w = tid >> 5;

    // trailing blocks: convert W_out to f16 (zero-padded rows >= VOC)
    if ((int)blockIdx.x >= PROJ_TILES) {
        int cid = ((int)blockIdx.x - PROJ_TILES) * 4 + blockIdx.y;  // 0..7
        const uint4 z = {0, 0, 0, 0};
        int base = cid * (VPAD * JD / 8 / 8);
        for (int i = tid; i < VPAD * JD / 8 / 8; i += 256) {
            int idx = base + i;
            reinterpret_cast<uint4*>(g_Wout)[idx] = (idx < VOC * JD / 8) ? pack8(wo + (size_t)idx * 8) : z;
        }
        return;
    }

    int m0 = (w & 3) * 32, n0 = (w >> 2) * 64;   // 4 m-warps x 2 n-warps, N-tile 128
    bool isenc = (int)blockIdx.x < ENC_TILES;
    int tile = isenc ? blockIdx.x : blockIdx.x - ENC_TILES;
    int nq = blockIdx.y;                          // N quarter (0..3)
    const float* Xf = (isenc ? xe : xd) + (size_t)tile * 128 * JD;
    const float* Wf = (isenc ? we : wd) + (size_t)nq * 128 * JD;
    int xrows = (isenc ? ENCR : DECR) - tile * 128;
    const float* bias = isenc ? be : bd;
    float* out = (isenc ? g_enc : g_dec) + (size_t)tile * 128 * JD;

    float* sbias = (float*)(smem + SM_BIAS);
    for (int i = tid; i < 512; i += 256) sbias[i] = bias[i];

    Frag f;
    frag_zero(f);
    const uint4 z = {0, 0, 0, 0};

    for (int c = 0; c < 8; c++) {
        int kc = c * 64;
        __syncthreads();
        #pragma unroll
        for (int i = tid; i < 1024; i += 256) {
            int r = i >> 3, j = i & 7;
            uint4 v = (r < xrows) ? pack8(Xf + (size_t)r * JD + kc + j * 8) : z;
            *reinterpret_cast<uint4*>(smem + SM_A0 + sw128(r * 128 + j * 16)) = v;
        }
        #pragma unroll
        for (int i = tid; i < 1024; i += 256) {
            int r = i >> 3, j = i & 7;
            uint4 v = pack8(Wf + (size_t)r * JD + kc + j * 8);
            *reinterpret_cast<uint4*>(smem + SM_B0 + sw128(r * 128 + j * 16)) = v;
        }
        __syncthreads();
        mma_chunk64(f, sb + SM_A0, sb + SM_B0, lane, m0, n0);
    }

    #pragma unroll
    for (int mt = 0; mt < 2; mt++) {
        int grow = m0 + mt * 16 + (lane >> 2);
        #pragma unroll
        for (int nt = 0; nt < 8; nt++) {
            int col = n0 + nt * 8 + (lane & 3) * 2;
            int gcol = nq * 128 + col;
            float2 v0 = { f.acc[mt][nt][0] + sbias[gcol], f.acc[mt][nt][1] + sbias[gcol + 1] };
            float2 v1 = { f.acc[mt][nt][2] + sbias[gcol], f.acc[mt][nt][3] + sbias[gcol + 1] };
            *reinterpret_cast<float2*>(out + (size_t)grow * JD + gcol) = v0;
            *reinterpret_cast<float2*>(out + (size_t)(grow + 8) * JD + gcol) = v1;
        }
    }
}

// ---------------- kernel 2: fused tanh-join + output GEMM (2 CTAs/SM) ----------------
// B stage: 256 N-rows x 32 K (f16), 64B rows, SW64 swizzle, via cp.async.
DEVINL void issueB(uint32_t sb, int buf, int s, int tid) {
    int nh = s >> 4, c2 = s & 15;                 // c2 = K32 chunk index
    const __half* W = g_Wout + (size_t)nh * 256 * JD + c2 * 32;
    uint32_t base = sb + (buf ? JSM_B1 : JSM_B0);
    #pragma unroll
    for (int i = tid; i < 1024; i += 256) {
        int r = i >> 2, j = i & 3;
        cpasync16(base + sw64((uint32_t)(r * 64 + j * 16)), W + (size_t)r * JD + j * 8);
    }
    cpcommit();
}

__global__ void __launch_bounds__(256, 2) joiner_join(const float* __restrict__ bo,
                                                      float* __restrict__ out) {
    extern __shared__ char smem[];
    uint32_t sb = s2u(smem);
    int tid = threadIdx.x, lane = tid & 31, w = tid >> 5;
    int m0 = (w & 1) * 32, n0 = (w >> 1) * 64;
    int tile = blockIdx.x;

    int* eoff = (int*)(smem + JSM_EOFF);
    int* doff = (int*)(smem + JSM_DOFF);
    if (tid < 64) {
        int r = tile * JT_M + tid;
        int n = r / (TT * UU), rem = r % (TT * UU);
        int t = rem / UU, u = rem % UU;
        eoff[tid] = (n * TT + t) * JD;
        doff[tid] = (n * UU + u) * JD;
    }
    float* sbias = (float*)(smem + JSM_BIAS);
    for (int i = tid; i < 512; i += 256) sbias[i] = (i < VOC) ? bo[i] : 0.f;

    issueB(sb, 0, 0, tid);      // B stage 0 (async, overlaps A generation)
    __syncthreads();            // eoff/doff visible

    // Generate A ONCE: fp16(tanh(enc+dec)), 64 rows x 512 cols, 8 resident
    // sw128 chunks of 8KB (64 rows x 128B).
    for (int i = tid; i < 4096; i += 256) {
        int c = i >> 9, r = (i >> 3) & 63, j = i & 7;
        int k = c * 64 + j * 8;
        const float* e = g_enc + eoff[r] + k;
        const float* d = g_dec + doff[r] + k;
        float4 e0 = *reinterpret_cast<const float4*>(e);
        float4 e1 = *reinterpret_cast<const float4*>(e + 4);
        float4 d0 = *reinterpret_cast<const float4*>(d);
        float4 d1 = *reinterpret_cast<const float4*>(d + 4);
        uint4 v;
        v.x = h2_bits(__floats2half2_rn(tanh_fast(e0.x + d0.x), tanh_fast(e0.y + d0.y)));
        v.y = h2_bits(__floats2half2_rn(tanh_fast(e0.z + d0.z), tanh_fast(e0.w + d0.w)));
        v.z = h2_bits(__floats2half2_rn(tanh_fast(e1.x + d1.x), tanh_fast(e1.y + d1.y)));
        v.w = h2_bits(__floats2half2_rn(tanh_fast(e1.z + d1.z), tanh_fast(e1.w + d1.w)));
        *reinterpret_cast<uint4*>(smem + JSM_A + c * 8192 + sw128(r * 128 + j * 16)) = v;
    }

    Frag f;
    frag_zero(f);

    // 32 stages: nh (2) x K32 chunks (16). A chunk = c2>>1, in-row offset (c2&1)*64 B.
    for (int s = 0; s < 32; s++) {
        int c2 = s & 15, buf = s & 1;
        if (s < 31) {
            issueB(sb, buf ^ 1, s + 1, tid);
            cpwait<1>();
        } else {
            cpwait<0>();
        }
        __syncthreads();  // B[buf] complete + (s==0) A visible to all warps
        mma_chunk32(f, sb + JSM_A + (c2 >> 1) * 8192, (c2 & 1) * 64,
                    sb + (buf ? JSM_B1 : JSM_B0), lane, m0, n0);

        if (c2 == 15) {
            int nh = s >> 4;
            #pragma unroll
            for (int mt = 0; mt < 2; mt++) {
                int grow = tile * JT_M + m0 + mt * 16 + (lane >> 2);
                #pragma unroll
                for (int nt = 0; nt < 8; nt++) {
                    int col = n0 + nt * 8 + (lane & 3) * 2;
                    int gcol = nh * 256 + col;
                    if (gcol < VOC) {
                        float2 v0 = { f.acc[mt][nt][0] + sbias[gcol], f.acc[mt][nt][1] + sbias[gcol + 1] };
                        float2 v1 = { f.acc[mt][nt][2] + sbias[gcol], f.acc[mt][nt][3] + sbias[gcol + 1] };
                        *reinterpret_cast<float2*>(out + (size_t)grow * VOC + gcol) = v0;
                        *reinterpret_cast<float2*>(out + (size_t)(grow + 8) * VOC + gcol) = v1;
                    }
                }
            }
            frag_zero(f);
        }
        __syncthreads();  // all warps done reading B[buf] before it is refilled
    }
}

extern "C" void kernel_launch(void* const* d_in, const int* in_sizes, int n_in,
                              void* d_out, int out_size) {
    const float* enc = (const float*)d_in[0];
    const float* dec = (const float*)d_in[1];
    const float* We  = (const float*)d_in[2];
    const float* be  = (const float*)d_in[3];
    const float* Wd  = (const float*)d_in[4];
    const float* bd  = (const float*)d_in[5];
    const float* Wo  = (const float*)d_in[6];
    const float* bo  = (const float*)d_in[7];
    float* out = (float*)d_out;

    cudaFuncSetAttribute(joiner_proj, cudaFuncAttributeMaxDynamicSharedMemorySize, PROJ_SMEM);
    cudaFuncSetAttribute(joiner_join, cudaFuncAttributeMaxDynamicSharedMemorySize, JOIN_SMEM);

    joiner_proj<<<dim3(PROJ_TILES + 2, 4), 256, PROJ_SMEM>>>(enc, dec, We, Wd, Wo, be, bd);
    joiner_join<<<JTILES, 256, JOIN_SMEM>>>(bo, out);
}

// round 16
// speedup vs baseline: 1.2761x; 1.0191x over previous
#include <cuda_runtime.h>
#include <cuda_fp16.h>
#include <cstdint>
#include <cstddef>

#define DEVINL __device__ __forceinline__

constexpr int JD = 512, VOC = 500, VPAD = 512;
constexpr int NB = 8, TT = 200, UU = 50;
constexpr int ENCR = NB * TT;          // 1600
constexpr int ENCRP = 1664;            // 13*128
constexpr int DECR = NB * UU;          // 400
constexpr int ENC_TILES = ENCRP / 128; // 13
constexpr int DEC_TILES = 4;           // 512/128
constexpr int PROJ_TILES = ENC_TILES + DEC_TILES; // 17
constexpr int MTOT = NB * TT * UU;     // 80000
constexpr int JT_M = 64;
constexpr int JTILES = MTOT / JT_M;    // 1250

// ---- device scratch (no allocs allowed) ----
__device__ __align__(16) __half g_Wout[VPAD * JD];
__device__ __align__(16) float  g_enc[ENCRP * JD];
__device__ __align__(16) float  g_dec[512 * JD];

// ---- smem layout: proj kernel ----
constexpr int SM_BIAS = 1024;   // 512 float
constexpr int SM_A0   = 4096;   // 128x64 f16 sw128 = 16KB
constexpr int SM_B0   = 20480;  // 128x64 f16 sw128 = 16KB
constexpr int PROJ_SMEM = 36864;

// ---- smem layout: join kernel (A resident, B 3-deep K32 ring) ----
constexpr int JSM_EOFF = 0;       // 64 int
constexpr int JSM_DOFF = 256;     // 64 int
constexpr int JSM_A    = 512;               // 8 chunks x 8KB = 64KB (128B-aligned base)
constexpr int JSM_B    = JSM_A + 65536;     // 66048; 3 x 16KB ring (256x32 f16 sw64)
constexpr int JSM_BSZ  = 16384;
constexpr int JOIN_SMEM = JSM_B + 3 * JSM_BSZ; // 115200 -> 2 CTAs/SM

DEVINL uint32_t s2u(const void* p) { return (uint32_t)__cvta_generic_to_shared(p); }
DEVINL uint32_t sw128(uint32_t o) { return o ^ ((o >> 3) & 0x70); }
DEVINL uint32_t sw64(uint32_t o)  { return o ^ ((o >> 3) & 0x30); }
DEVINL float tanh_fast(float x) { float y; asm("tanh.approx.f32 %0, %1;" : "=f"(y) : "f"(x)); return y; }
DEVINL uint32_t h2_bits(__half2 h) { return *reinterpret_cast<uint32_t*>(&h); }

DEVINL void ldsm4(uint32_t* r, uint32_t addr) {
    asm volatile("ldmatrix.sync.aligned.m8n8.x4.shared.b16 {%0,%1,%2,%3}, [%4];"
                 : "=r"(r[0]), "=r"(r[1]), "=r"(r[2]), "=r"(r[3]) : "r"(addr));
}
DEVINL void mma16816(float* c, const uint32_t* a, uint32_t b0, uint32_t b1) {
    asm volatile(
        "mma.sync.aligned.m16n8k16.row.col.f32.f16.f16.f32 "
        "{%0,%1,%2,%3}, {%4,%5,%6,%7}, {%8,%9}, {%0,%1,%2,%3};"
        : "+f"(c[0]), "+f"(c[1]), "+f"(c[2]), "+f"(c[3])
        : "r"(a[0]), "r"(a[1]), "r"(a[2]), "r"(a[3]), "r"(b0), "r"(b1));
}
DEVINL void cpasync16(uint32_t dst, const void* src) {
    asm volatile("cp.async.cg.shared.global [%0], [%1], 16;" :: "r"(dst), "l"(src));
}
DEVINL void cpcommit() { asm volatile("cp.async.commit_group;" ::: "memory"); }
template <int N> DEVINL void cpwait() { asm volatile("cp.async.wait_group %0;" :: "n"(N) : "memory"); }

DEVINL uint4 pack8(const float* src) {
    float4 a = *reinterpret_cast<const float4*>(src);
    float4 b = *reinterpret_cast<const float4*>(src + 4);
    uint4 o;
    o.x = h2_bits(__floats2half2_rn(a.x, a.y));
    o.y = h2_bits(__floats2half2_rn(a.z, a.w));
    o.z = h2_bits(__floats2half2_rn(b.x, b.y));
    o.w = h2_bits(__floats2half2_rn(b.z, b.w));
    return o;
}

// ---------------- HMMA fragments ----------------
struct Frag { float acc[2][8][4]; };

DEVINL void frag_zero(Frag& f) {
    #pragma unroll
    for (int mt = 0; mt < 2; mt++)
        #pragma unroll
        for (int nt = 0; nt < 8; nt++)
            #pragma unroll
            for (int q = 0; q < 4; q++) f.acc[mt][nt][q] = 0.f;
}

// K=64 chunk, A+B both sw128 128B rows (proj kernel). Warp tile 32Mx64N.
DEVINL void mma_chunk64(Frag& f, uint32_t sA, uint32_t sB, int lane, int m0, int n0) {
    int arow = m0 + (lane & 15);
    int acolb = (lane >> 4) * 16;
    int brow = n0 + ((lane >> 4) << 3) + (lane & 7);
    int bcolb = ((lane >> 3) & 1) * 16;
    #pragma unroll
    for (int kk = 0; kk < 4; kk++) {
        uint32_t afr[2][4];
        ldsm4(afr[0], sA + sw128((uint32_t)(arow * 128 + kk * 32 + acolb)));
        ldsm4(afr[1], sA + sw128((uint32_t)((arow + 16) * 128 + kk * 32 + acolb)));
        uint32_t bfr[4][4];
        #pragma unroll
        for (int q = 0; q < 4; q++)
            ldsm4(bfr[q], sB + sw128((uint32_t)((brow + q * 16) * 128 + kk * 32 + bcolb)));
        #pragma unroll
        for (int mt = 0; mt < 2; mt++)
            #pragma unroll
            for (int nt = 0; nt < 8; nt++)
                mma16816(f.acc[mt][nt], afr[mt], bfr[nt >> 1][(nt & 1) * 2], bfr[nt >> 1][(nt & 1) * 2 + 1]);
    }
}

// K=32 stage (join): A sw128 128B rows with byte offset koff; B sw64 64B rows.
DEVINL void mma_chunk32(Frag& f, uint32_t sA, int koff, uint32_t sB, int lane, int m0, int n0) {
    int arow = m0 + (lane & 15);
    int acolb = (lane >> 4) * 16;
    int brow = n0 + ((lane >> 4) << 3) + (lane & 7);
    int bcolb = ((lane >> 3) & 1) * 16;
    #pragma unroll
    for (int kk = 0; kk < 2; kk++) {
        uint32_t afr[2][4];
        ldsm4(afr[0], sA + sw128((uint32_t)(arow * 128 + koff + kk * 32 + acolb)));
        ldsm4(afr[1], sA + sw128((uint32_t)((arow + 16) * 128 + koff + kk * 32 + acolb)));
        uint32_t bfr[4][4];
        #pragma unroll
        for (int q = 0; q < 4; q++)
            ldsm4(bfr[q], sB + sw64((uint32_t)((brow + q * 16) * 64 + kk * 32 + bcolb)));
        #pragma unroll
        for (int mt = 0; mt < 2; mt++)
            #pragma unroll
            for (int nt = 0; nt < 8; nt++)
                mma16816(f.acc[mt][nt], afr[mt], bfr[nt >> 1][(nt & 1) * 2], bfr[nt >> 1][(nt & 1) * 2 + 1]);
    }
}

// ---------------- kernel 1: projections (inline fp32->f16) + Wout convert ----------------
__global__ void __launch_bounds__(256, 2) joiner_proj(
    const float* __restrict__ xe, const float* __restrict__ xd,
    const float* __restrict__ we, const float* __restrict__ wd,
    const float* __restrict__ wo,
    const float* __restrict__ be, const float* __restrict__ bd) {
    extern __shared__ char smem[];
    uint32_t sb = s2u(smem);
    int tid = threadIdx.x, lane = tid & 31, w = tid >> 5;

    // trailing blocks: convert W_out to f16 (zero-padded rows >= VOC)
    if ((int)blockIdx.x >= PROJ_TILES) {
        int cid = ((int)blockIdx.x - PROJ_TILES) * 4 + blockIdx.y;  // 0..7
        const uint4 z = {0, 0, 0, 0};
        int base = cid * (VPAD * JD / 8 / 8);
        for (int i = tid; i < VPAD * JD / 8 / 8; i += 256) {
            int idx = base + i;
            reinterpret_cast<uint4*>(g_Wout)[idx] = (idx < VOC * JD / 8) ? pack8(wo + (size_t)idx * 8) : z;
        }
        return;
    }

    int m0 = (w & 3) * 32, n0 = (w >> 2) * 64;   // 4 m-warps x 2 n-warps, N-tile 128
    bool isenc = (int)blockIdx.x < ENC_TILES;
    int tile = isenc ? blockIdx.x : blockIdx.x - ENC_TILES;
    int nq = blockIdx.y;                          // N quarter (0..3)
    const float* Xf = (isenc ? xe : xd) + (size_t)tile * 128 * JD;
    const float* Wf = (isenc ? we : wd) + (size_t)nq * 128 * JD;
    int xrows = (isenc ? ENCR : DECR) - tile * 128;
    const float* bias = isenc ? be : bd;
    float* out = (isenc ? g_enc : g_dec) + (size_t)tile * 128 * JD;

    float* sbias = (float*)(smem + SM_BIAS);
    for (int i = tid; i < 512; i += 256) sbias[i] = bias[i];

    Frag f;
    frag_zero(f);
    const uint4 z = {0, 0, 0, 0};

    for (int c = 0; c < 8; c++) {
        int kc = c * 64;
        __syncthreads();
        #pragma unroll
        for (int i = tid; i < 1024; i += 256) {
            int r = i >> 3, j = i & 7;
            uint4 v = (r < xrows) ? pack8(Xf + (size_t)r * JD + kc + j * 8) : z;
            *reinterpret_cast<uint4*>(smem + SM_A0 + sw128(r * 128 + j * 16)) = v;
        }
        #pragma unroll
        for (int i = tid; i < 1024; i += 256) {
            int r = i >> 3, j = i & 7;
            uint4 v = pack8(Wf + (size_t)r * JD + kc + j * 8);
            *reinterpret_cast<uint4*>(smem + SM_B0 + sw128(r * 128 + j * 16)) = v;
        }
        __syncthreads();
        mma_chunk64(f, sb + SM_A0, sb + SM_B0, lane, m0, n0);
    }

    #pragma unroll
    for (int mt = 0; mt < 2; mt++) {
        int grow = m0 + mt * 16 + (lane >> 2);
        #pragma unroll
        for (int nt = 0; nt < 8; nt++) {
            int col = n0 + nt * 8 + (lane & 3) * 2;
            int gcol = nq * 128 + col;
            float2 v0 = { f.acc[mt][nt][0] + sbias[gcol], f.acc[mt][nt][1] + sbias[gcol + 1] };
            float2 v1 = { f.acc[mt][nt][2] + sbias[gcol], f.acc[mt][nt][3] + sbias[gcol + 1] };
            *reinterpret_cast<float2*>(out + (size_t)grow * JD + gcol) = v0;
            *reinterpret_cast<float2*>(out + (size_t)(grow + 8) * JD + gcol) = v1;
        }
    }
}

// ---------------- kernel 2: fused tanh-join + output GEMM (2 CTAs/SM) ----------------
// B stage s (s = nh*16 + c2): 256 N-rows x 32 K f16, 64B rows, SW64, cp.async.
DEVINL void issueB(uint32_t sb, int s, int tid) {
    int nh = s >> 4, c2 = s & 15;
    const __half* W = g_Wout + (size_t)nh * 256 * JD + c2 * 32;
    uint32_t base = sb + JSM_B + (s % 3) * JSM_BSZ;
    #pragma unroll
    for (int i = tid; i < 1024; i += 256) {
        int r = i >> 2, j = i & 3;
        cpasync16(base + sw64((uint32_t)(r * 64 + j * 16)), W + (size_t)r * JD + j * 8);
    }
    cpcommit();
}

__global__ void __launch_bounds__(256, 2) joiner_join(const float* __restrict__ bo,
                                                      float* __restrict__ out) {
    extern __shared__ char smem[];
    uint32_t sb = s2u(smem);
    int tid = threadIdx.x, lane = tid & 31, w = tid >> 5;
    int m0 = (w & 1) * 32, n0 = (w >> 1) * 64;
    int tile = blockIdx.x;

    int* eoff = (int*)(smem + JSM_EOFF);
    int* doff = (int*)(smem + JSM_DOFF);
    if (tid < 64) {
        int r = tile * JT_M + tid;
        int n = r / (TT * UU), rem = r % (TT * UU);
        int t = rem / UU, u = rem % UU;
        eoff[tid] = (n * TT + t) * JD;
        doff[tid] = (n * UU + u) * JD;
    }

    issueB(sb, 0, tid);   // ring slots 0,1 in flight during A generation
    issueB(sb, 1, tid);
    __syncthreads();      // eoff/doff visible

    // Generate A ONCE: fp16(tanh(enc+dec)), 64 rows x 512 cols,
    // 8 resident sw128 chunks of 8KB (64 rows x 128B).
    for (int i = tid; i < 4096; i += 256) {
        int c = i >> 9, r = (i >> 3) & 63, j = i & 7;
        int k = c * 64 + j * 8;
        const float* e = g_enc + eoff[r] + k;
        const float* d = g_dec + doff[r] + k;
        float4 e0 = *reinterpret_cast<const float4*>(e);
        float4 e1 = *reinterpret_cast<const float4*>(e + 4);
        float4 d0 = *reinterpret_cast<const float4*>(d);
        float4 d1 = *reinterpret_cast<const float4*>(d + 4);
        uint4 v;
        v.x = h2_bits(__floats2half2_rn(tanh_fast(e0.x + d0.x), tanh_fast(e0.y + d0.y)));
        v.y = h2_bits(__floats2half2_rn(tanh_fast(e0.z + d0.z), tanh_fast(e0.w + d0.w)));
        v.z = h2_bits(__floats2half2_rn(tanh_fast(e1.x + d1.x), tanh_fast(e1.y + d1.y)));
        v.w = h2_bits(__floats2half2_rn(tanh_fast(e1.z + d1.z), tanh_fast(e1.w + d1.w)));
        *reinterpret_cast<uint4*>(smem + JSM_A + c * 8192 + sw128(r * 128 + j * 16)) = v;
    }

    Frag f;
    frag_zero(f);

    // 32 stages, ONE barrier per stage. Ring slot s%3; issue for s+2 goes into
    // slot (s+2)%3 == (s-1)%3, whose consumers (mma at stage s-1) are proven
    // done by the barrier at stage s.
    for (int s = 0; s < 32; s++) {
        int c2 = s & 15;
        if (s < 31) cpwait<1>(); else cpwait<0>();  // B[s] landed
        __syncthreads();                            // publish B[s] (+A at s=0); fence mma(s-1)
        if (s < 30) issueB(sb, s + 2, tid);
        mma_chunk32(f, sb + JSM_A + (c2 >> 1) * 8192, (c2 & 1) * 64,
                    sb + JSM_B + (s % 3) * JSM_BSZ, lane, m0, n0);

        if (c2 == 15) {
            int nh = s >> 4;
            #pragma unroll
            for (int mt = 0; mt < 2; mt++) {
                int grow = tile * JT_M + m0 + mt * 16 + (lane >> 2);
                #pragma unroll
                for (int nt = 0; nt < 8; nt++) {
                    int col = n0 + nt * 8 + (lane & 3) * 2;
                    int gcol = nh * 256 + col;
                    if (gcol < VOC) {
                        float b0v = __ldg(bo + gcol), b1v = __ldg(bo + gcol + 1);
                        float2 v0 = { f.acc[mt][nt][0] + b0v, f.acc[mt][nt][1] + b1v };
                        float2 v1 = { f.acc[mt][nt][2] + b0v, f.acc[mt][nt][3] + b1v };
                        *reinterpret_cast<float2*>(out + (size_t)grow * VOC + gcol) = v0;
                        *reinterpret_cast<float2*>(out + (size_t)(grow + 8) * VOC + gcol) = v1;
                    }
                }
            }
            frag_zero(f);
        }
    }
}

extern "C" void kernel_launch(void* const* d_in, const int* in_sizes, int n_in,
                              void* d_out, int out_size) {
    const float* enc = (const float*)d_in[0];
    const float* dec = (const float*)d_in[1];
    const float* We  = (const float*)d_in[2];
    const float* be  = (const float*)d_in[3];
    const float* Wd  = (const float*)d_in[4];
    const float* bd  = (const float*)d_in[5];
    const float* Wo  = (const float*)d_in[6];
    const float* bo  = (const float*)d_in[7];
    float* out = (float*)d_out;

    cudaFuncSetAttribute(joiner_proj, cudaFuncAttributeMaxDynamicSharedMemorySize, PROJ_SMEM);
    cudaFuncSetAttribute(joiner_join, cudaFuncAttributeMaxDynamicSharedMemorySize, JOIN_SMEM);

    joiner_proj<<<dim3(PROJ_TILES + 2, 4), 256, PROJ_SMEM>>>(enc, dec, We, Wd, Wo, be, bd);
    joiner_join<<<JTILES, 256, JOIN_SMEM>>>(bo, out);
}